// round 14
// baseline (speedup 1.0000x reference)
#include <cuda_runtime.h>
#include <cuda_fp16.h>
#include <mma.h>

using namespace nvcuda;

#define MAX_NODES 100000
#define MAX_EDGES 1600000
#define D 64

// ---- static device scratch (no allocations allowed) ----
__device__ unsigned long long g_degcnt[MAX_NODES];  // [40:64)=count, [0:40)=sum_w * 2^24
__device__ float   g_dis[MAX_NODES];
__device__ int     g_row_start[MAX_NODES];
__device__ int     g_cursor[MAX_NODES];
__device__ int     g_total;
__device__ int2    g_edge[MAX_EDGES];               // {src, w bits}
__device__ __half2 g_hA[MAX_NODES * 32];            // dis-scaled feature ping
__device__ __half2 g_hB[MAX_NODES * 32];            // dis-scaled feature pong
__device__ __half2 g_agg16[(MAX_NODES + 128) * 32]; // agg (fp16), padded for wmma tiles
__device__ int     g_is32;

#define WFIX 16777216.0f   // 2^24

// --- init degcnt + dtype detect ---
__global__ void k_prep(const long long* __restrict__ ei, int n) {
    int i = blockIdx.x * blockDim.x + threadIdx.x;
    if (i < n) g_degcnt[i] = (unsigned long long)WFIX;  // self-loop weight 1, count 0
    if (i == 0) g_total = 0;
    if (i < 256) {
        // int32 buffer read as int64 packs two ids -> values >= 2^32
        long long v = ei[i];
        if (v < 0 || v >= (long long)n) atomicOr(&g_is32, 1);
    }
}

__device__ __forceinline__ int load_idx(const void* ei, int pos, int is32, int n) {
    int v;
    if (is32) v = ((const int*)ei)[pos];
    else      v = (int)((const long long*)ei)[pos];
    return v < 0 ? 0 : (v >= n ? n - 1 : v);
}

// 2 edges/thread; one 64-bit RED per edge (count++ | fixed-point weight add)
__global__ void k_edge_deg(const void* __restrict__ ei,
                           const float* __restrict__ w, int E, int n) {
    int e = (blockIdx.x * blockDim.x + threadIdx.x) * 2;
    if (e >= E) return;
    int is32 = g_is32;
#pragma unroll
    for (int j = 0; j < 2; j++) {
        if (e + j < E) {
            int dst = load_idx(ei, E + e + j, is32, n);
            unsigned long long enc = ((unsigned long long)1 << 40)
                                   | (unsigned long long)(w[e + j] * WFIX + 0.5f);
            atomicAdd(&g_degcnt[dst], enc);
        }
    }
}

// --- single-pass offsets: block-local exclusive scan + atomic global base ---
// Also computes dis = rsqrt(deg).
__global__ void k_offsets(int n) {
    __shared__ int sh[1024];
    __shared__ int base_sh;
    int tid = threadIdx.x;
    int gid = blockIdx.x * 1024 + tid;
    int v = 0;
    if (gid < n) {
        unsigned long long dc = g_degcnt[gid];
        v = (int)(dc >> 40);
        float deg = (float)(dc & 0xFFFFFFFFFFull) * (1.0f / WFIX);
        g_dis[gid] = rsqrtf(deg);            // deg >= 1 always
    }
    sh[tid] = v;
    __syncthreads();
    for (int off = 1; off < 1024; off <<= 1) {
        int t = (tid >= off) ? sh[tid - off] : 0;
        __syncthreads();
        sh[tid] += t;
        __syncthreads();
    }
    if (tid == 1023) base_sh = atomicAdd(&g_total, sh[1023]);
    __syncthreads();
    if (gid < n) {
        int s = base_sh + sh[tid] - v;
        g_row_start[gid] = s;
        g_cursor[gid]    = s;
    }
}

// --- x fp32 -> dis-scaled fp16, vectorized: one float4 (4 cols) per thread ---
__global__ void k_convert(const float* __restrict__ x, int nq) {
    int i = blockIdx.x * blockDim.x + threadIdx.x;   // float4 elements
    if (i < nq) {
        float dis = g_dis[i >> 4];                   // 16 float4 per row
        float4 v = ((const float4*)x)[i];
        __half2 o0 = __floats2half2_rn(v.x * dis, v.y * dis);
        __half2 o1 = __floats2half2_rn(v.z * dis, v.w * dis);
        uint2 st;
        st.x = *reinterpret_cast<unsigned*>(&o0);
        st.y = *reinterpret_cast<unsigned*>(&o1);
        ((uint2*)g_hA)[i] = st;
    }
}

// --- CSR-by-dst scatter: record = (src, raw weight). 2 edges/thread. ---
__global__ void k_build(const void* __restrict__ ei,
                        const float* __restrict__ w, int E, int n) {
    int e = (blockIdx.x * blockDim.x + threadIdx.x) * 2;
    if (e >= E) return;
    int is32 = g_is32;
#pragma unroll
    for (int j = 0; j < 2; j++) {
        if (e + j < E) {
            int s = load_idx(ei, e + j, is32, n);
            int d = load_idx(ei, E + e + j, is32, n);
            int pos = atomicAdd(&g_cursor[d], 1);
            g_edge[pos] = make_int2(s, __float_as_int(w[e + j]));
        }
    }
}

__device__ __forceinline__ void acc_row(float4& acc, uint2 v, float nm) {
    __half2 h0, h1;
    *reinterpret_cast<unsigned*>(&h0) = v.x;
    *reinterpret_cast<unsigned*>(&h1) = v.y;
    float2 a = __half22float2(h0);
    float2 b = __half22float2(h1);
    acc.x += a.x * nm; acc.y += a.y * nm;
    acc.z += b.x * nm; acc.w += b.y * nm;
}

// --- aggregation: 2 nodes per warp (16 lanes each, 8B/lane) ---
// Masked full 8-edge batches: the tail is padded (clamped index, zero weight)
// so all 8 record->feature chains stay in flight even on the last batch.
// Features are dis-scaled (hs = dis*h); agg = dis[d] * (hs[d] + sum w*hs[src]).
// io_mode: 0/2 read g_hA, 1 read g_hB. Writes g_agg16.
__global__ void k_gather(int io_mode, int n) {
    const uint2* hv = (const uint2*)((io_mode == 1) ? g_hB : g_hA);
    int warpId = (blockIdx.x * blockDim.x + threadIdx.x) >> 5;
    int lane = threadIdx.x & 31;
    int g = lane >> 4;          // node slot within warp
    int l = lane & 15;          // uint2 column index (4 cols)
    int node = warpId * 2 + g;
    if (node >= n) return;

    float4 acc = make_float4(0.f, 0.f, 0.f, 0.f);
    acc_row(acc, hv[node * 16 + l], 1.0f);    // self-loop term (weight 1)

    int e   = g_row_start[node];
    int end = g_cursor[node];
    while (e < end) {
        int2 r[8];
#pragma unroll
        for (int j = 0; j < 8; j++) {
            int idx = e + j;
            r[j] = g_edge[idx < end ? idx : end - 1];
            if (idx >= end) r[j].y = 0;       // zero weight for padded slots
        }
        uint2 v[8];
#pragma unroll
        for (int j = 0; j < 8; j++) v[j] = hv[r[j].x * 16 + l];
#pragma unroll
        for (int j = 0; j < 8; j++) acc_row(acc, v[j], __int_as_float(r[j].y));
        e += 8;
    }

    float dis = g_dis[node];
    acc.x *= dis; acc.y *= dis; acc.z *= dis; acc.w *= dis;

    __half2 o0 = __floats2half2_rn(acc.x, acc.y);
    __half2 o1 = __floats2half2_rn(acc.z, acc.w);
    uint2 st;
    st.x = *reinterpret_cast<unsigned*>(&o0);
    st.y = *reinterpret_cast<unsigned*>(&o1);
    ((uint2*)g_agg16)[node * 16 + l] = st;
}

// --- tensor-core GEMM (agg16 @ W) + bias (+relu) ---
// 256 thr = 8 warps; block does 128 rows x 64 cols. Warp w owns rows [w*16, w*16+16).
// io_mode 0/1: output = dis * relu(...) stored fp16 (pre-scaled for next hop).
// io_mode 2:   output = (...) stored fp32, unscaled.
__global__ void __launch_bounds__(256) k_gemm(
    const float* __restrict__ W, const float* __restrict__ b,
    float* __restrict__ outf, int io_mode, int n)
{
    __half2* outh = (io_mode == 0) ? g_hB : (io_mode == 1 ? g_hA : nullptr);
    int relu = (io_mode != 2);

    __shared__ __half Wh[64 * 64];          // 8KB, row-major [k][c], ld=64
    __shared__ float  Cbuf[8][16][72];      // 36KB, per-warp 16x64 (+pad)

    int tid  = threadIdx.x;
    int warp = tid >> 5;
    int lane = tid & 31;
    int row0 = blockIdx.x * 128;

    for (int i = tid; i < 4096; i += 256)
        Wh[i] = __float2half(W[i]);
    __syncthreads();

    const __half* ABase = reinterpret_cast<const __half*>(g_agg16);
    int rbase = row0 + warp * 16;           // padding rows in g_agg16 stay zero

    wmma::fragment<wmma::accumulator, 16, 16, 16, float> c[4];
#pragma unroll
    for (int j = 0; j < 4; j++) wmma::fill_fragment(c[j], 0.0f);

#pragma unroll
    for (int kt = 0; kt < 4; kt++) {
        wmma::fragment<wmma::matrix_a, 16, 16, 16, __half, wmma::row_major> a;
        wmma::load_matrix_sync(a, ABase + rbase * 64 + kt * 16, 64);
#pragma unroll
        for (int j = 0; j < 4; j++) {
            wmma::fragment<wmma::matrix_b, 16, 16, 16, __half, wmma::row_major> bf;
            wmma::load_matrix_sync(bf, &Wh[(kt * 16) * 64 + j * 16], 64);
            wmma::mma_sync(c[j], a, bf, c[j]);
        }
    }
#pragma unroll
    for (int j = 0; j < 4; j++)
        wmma::store_matrix_sync(&Cbuf[warp][0][j * 16], c[j], 72, wmma::mem_row_major);
    __syncwarp();

    // epilogue: each lane handles one row-half (16 rows x 2 halves = 32 lanes)
    int r    = lane & 15;
    int half = lane >> 4;          // cols [half*32, half*32+32)
    int grow = rbase + r;
    if (grow < n) {
        float dis = (io_mode != 2) ? g_dis[grow] : 1.0f;
        int cbase = half * 32;
#pragma unroll
        for (int j = 0; j < 8; j++) {
            int cc = cbase + j * 4;
            float4 v = *(const float4*)&Cbuf[warp][r][cc];
            float4 bv = *(const float4*)&b[cc];
            v.x += bv.x; v.y += bv.y; v.z += bv.z; v.w += bv.w;
            if (relu) {
                v.x = fmaxf(v.x, 0.f); v.y = fmaxf(v.y, 0.f);
                v.z = fmaxf(v.z, 0.f); v.w = fmaxf(v.w, 0.f);
            }
            if (outh) {
                v.x *= dis; v.y *= dis; v.z *= dis; v.w *= dis;
                outh[grow * 32 + (cc >> 1)]     = __floats2half2_rn(v.x, v.y);
                outh[grow * 32 + (cc >> 1) + 1] = __floats2half2_rn(v.z, v.w);
            } else {
                *(float4*)&outf[grow * 64 + cc] = v;
            }
        }
    }
}

// ---------------------------------------------------------------------------
extern "C" void kernel_launch(void* const* d_in, const int* in_sizes, int n_in,
                              void* d_out, int out_size) {
    const float* x  = (const float*)d_in[0];
    const void*  ei = d_in[1];
    const float* w  = (const float*)d_in[2];
    const float* W1 = (const float*)d_in[3];
    const float* b1 = (const float*)d_in[4];
    const float* W2 = (const float*)d_in[5];
    const float* b2 = (const float*)d_in[6];
    const float* W3 = (const float*)d_in[7];
    const float* b3 = (const float*)d_in[8];
    float* out = (float*)d_out;

    int n = in_sizes[0] / D;      // 100000
    int E = in_sizes[1] / 2;      // 1600000

    const int tb = 256;
    int nq = n * 16;                         // float4 elements of feature matrix
    int nblk_n = (n + tb - 1) / tb;
    int nblk_c = (nq + tb - 1) / tb;
    int nblk_e2 = (E / 2 + tb - 1) / tb;     // 2 edges per thread
    int nb = (n + 1023) / 1024;

    k_prep<<<nblk_n, tb>>>((const long long*)ei, n);
    k_edge_deg<<<nblk_e2, tb>>>(ei, w, E, n);
    k_offsets<<<nb, 1024>>>(n);
    k_convert<<<nblk_c, tb>>>(x, nq);
    k_build<<<nblk_e2, tb>>>(ei, w, E, n);

    int gblocks = (n * 16 + tb - 1) / tb;   // 2 nodes per warp
    int mblocks = (n + 127) / 128;

    // layer1: hA -> agg -> hB ; layer2: hB -> agg -> hA ; layer3: hA -> out
    k_gather<<<gblocks, tb>>>(0, n);
    k_gemm<<<mblocks, 256>>>(W1, b1, nullptr, 0, n);
    k_gather<<<gblocks, tb>>>(1, n);
    k_gemm<<<mblocks, 256>>>(W2, b2, nullptr, 1, n);
    k_gather<<<gblocks, tb>>>(0, n);
    k_gemm<<<mblocks, 256>>>(W3, b3, out, 2, n);
}

// round 15
// speedup vs baseline: 1.0739x; 1.0739x over previous
#include <cuda_runtime.h>
#include <cuda_fp16.h>
#include <mma.h>

using namespace nvcuda;

#define MAX_NODES 100000
#define MAX_EDGES 1600000
#define D 64

// ---- static device scratch (no allocations allowed) ----
__device__ unsigned long long g_degcnt[MAX_NODES];  // [40:64)=count, [0:40)=sum_w * 2^24
__device__ float   g_dis[MAX_NODES];
__device__ int     g_row_start[MAX_NODES];
__device__ int     g_cursor[MAX_NODES];
__device__ int     g_total;
__device__ int2    g_edge[MAX_EDGES];               // {src, w bits}
__device__ __half2 g_hA[MAX_NODES * 32];            // dis-scaled feature ping
__device__ __half2 g_hB[MAX_NODES * 32];            // dis-scaled feature pong
__device__ __half2 g_agg16[(MAX_NODES + 128) * 32]; // agg (fp16), padded for wmma tiles
__device__ int     g_is32;

#define WFIX 16777216.0f   // 2^24

// --- init degcnt + dtype detect ---
__global__ void k_prep(const long long* __restrict__ ei, int n) {
    int i = blockIdx.x * blockDim.x + threadIdx.x;
    if (i < n) g_degcnt[i] = (unsigned long long)WFIX;  // self-loop weight 1, count 0
    if (i == 0) g_total = 0;
    if (i < 256) {
        // int32 buffer read as int64 packs two ids -> values >= 2^32
        long long v = ei[i];
        if (v < 0 || v >= (long long)n) atomicOr(&g_is32, 1);
    }
}

__device__ __forceinline__ int load_idx(const void* ei, int pos, int is32, int n) {
    int v;
    if (is32) v = ((const int*)ei)[pos];
    else      v = (int)((const long long*)ei)[pos];
    return v < 0 ? 0 : (v >= n ? n - 1 : v);
}

// one 64-bit RED per edge: count++ (high bits) + fixed-point weight add (low bits)
__global__ void k_edge_deg(const void* __restrict__ ei,
                           const float* __restrict__ w, int E, int n) {
    int e = blockIdx.x * blockDim.x + threadIdx.x;
    if (e < E) {
        int is32 = g_is32;
        int dst = load_idx(ei, E + e, is32, n);
        unsigned long long enc = ((unsigned long long)1 << 40)
                               | (unsigned long long)(w[e] * WFIX + 0.5f);
        atomicAdd(&g_degcnt[dst], enc);
    }
}

// --- single-pass offsets: block-local exclusive scan + atomic global base ---
// Also computes dis = rsqrt(deg).
__global__ void k_offsets(int n) {
    __shared__ int sh[1024];
    __shared__ int base_sh;
    int tid = threadIdx.x;
    int gid = blockIdx.x * 1024 + tid;
    int v = 0;
    if (gid < n) {
        unsigned long long dc = g_degcnt[gid];
        v = (int)(dc >> 40);
        float deg = (float)(dc & 0xFFFFFFFFFFull) * (1.0f / WFIX);
        g_dis[gid] = rsqrtf(deg);            // deg >= 1 always
    }
    sh[tid] = v;
    __syncthreads();
    for (int off = 1; off < 1024; off <<= 1) {
        int t = (tid >= off) ? sh[tid - off] : 0;
        __syncthreads();
        sh[tid] += t;
        __syncthreads();
    }
    if (tid == 1023) base_sh = atomicAdd(&g_total, sh[1023]);
    __syncthreads();
    if (gid < n) {
        int s = base_sh + sh[tid] - v;
        g_row_start[gid] = s;
        g_cursor[gid]    = s;
    }
}

// --- x fp32 -> dis-scaled fp16, vectorized: one float4 (4 cols) per thread ---
__global__ void k_convert(const float* __restrict__ x, int nq) {
    int i = blockIdx.x * blockDim.x + threadIdx.x;   // float4 elements
    if (i < nq) {
        float dis = g_dis[i >> 4];                   // 16 float4 per row
        float4 v = ((const float4*)x)[i];
        __half2 o0 = __floats2half2_rn(v.x * dis, v.y * dis);
        __half2 o1 = __floats2half2_rn(v.z * dis, v.w * dis);
        uint2 st;
        st.x = *reinterpret_cast<unsigned*>(&o0);
        st.y = *reinterpret_cast<unsigned*>(&o1);
        ((uint2*)g_hA)[i] = st;
    }
}

// --- CSR-by-dst scatter: record = (src, raw weight). No dis loads. ---
__global__ void k_build(const void* __restrict__ ei,
                        const float* __restrict__ w, int E, int n) {
    int e = blockIdx.x * blockDim.x + threadIdx.x;
    if (e < E) {
        int is32 = g_is32;
        int s = load_idx(ei, e, is32, n);
        int d = load_idx(ei, E + e, is32, n);
        int pos = atomicAdd(&g_cursor[d], 1);
        g_edge[pos] = make_int2(s, __float_as_int(w[e]));
    }
}

__device__ __forceinline__ void acc_row(float4& acc, uint2 v, float nm) {
    __half2 h0, h1;
    *reinterpret_cast<unsigned*>(&h0) = v.x;
    *reinterpret_cast<unsigned*>(&h1) = v.y;
    float2 a = __half22float2(h0);
    float2 b = __half22float2(h1);
    acc.x += a.x * nm; acc.y += a.y * nm;
    acc.z += b.x * nm; acc.w += b.y * nm;
}

// --- aggregation: 2 nodes per warp (16 lanes each, 8B/lane), 8-edge batches ---
// Features are dis-scaled (hs = dis*h); agg = dis[d] * (hs[d] + sum w*hs[src]).
// io_mode: 0/2 read g_hA, 1 read g_hB. Writes g_agg16.
__global__ void k_gather(int io_mode, int n) {
    const uint2* hv = (const uint2*)((io_mode == 1) ? g_hB : g_hA);
    int warpId = (blockIdx.x * blockDim.x + threadIdx.x) >> 5;
    int lane = threadIdx.x & 31;
    int g = lane >> 4;          // node slot within warp
    int l = lane & 15;          // uint2 column index (4 cols)
    int node = warpId * 2 + g;
    if (node >= n) return;

    float4 acc = make_float4(0.f, 0.f, 0.f, 0.f);
    acc_row(acc, hv[node * 16 + l], 1.0f);    // self-loop term (weight 1)

    int e   = g_row_start[node];
    int end = g_cursor[node];
    while (end - e >= 8) {
        int2 r[8];
#pragma unroll
        for (int j = 0; j < 8; j++) r[j] = g_edge[e + j];
        uint2 v[8];
#pragma unroll
        for (int j = 0; j < 8; j++) v[j] = hv[r[j].x * 16 + l];
#pragma unroll
        for (int j = 0; j < 8; j++) acc_row(acc, v[j], __int_as_float(r[j].y));
        e += 8;
    }
    for (; e < end; e++) {
        int2 r0 = g_edge[e];
        acc_row(acc, hv[r0.x * 16 + l], __int_as_float(r0.y));
    }

    float dis = g_dis[node];
    acc.x *= dis; acc.y *= dis; acc.z *= dis; acc.w *= dis;

    __half2 o0 = __floats2half2_rn(acc.x, acc.y);
    __half2 o1 = __floats2half2_rn(acc.z, acc.w);
    uint2 st;
    st.x = *reinterpret_cast<unsigned*>(&o0);
    st.y = *reinterpret_cast<unsigned*>(&o1);
    ((uint2*)g_agg16)[node * 16 + l] = st;
}

// --- tensor-core GEMM (agg16 @ W) + bias (+relu) ---
// 256 thr = 8 warps; block does 128 rows x 64 cols. Warp w owns rows [w*16, w*16+16).
// io_mode 0/1: output = dis * relu(...) stored fp16 (pre-scaled for next hop).
// io_mode 2:   output = (...) stored fp32, unscaled.
__global__ void __launch_bounds__(256) k_gemm(
    const float* __restrict__ W, const float* __restrict__ b,
    float* __restrict__ outf, int io_mode, int n)
{
    __half2* outh = (io_mode == 0) ? g_hB : (io_mode == 1 ? g_hA : nullptr);
    int relu = (io_mode != 2);

    __shared__ __half Wh[64 * 64];          // 8KB, row-major [k][c], ld=64
    __shared__ float  Cbuf[8][16][72];      // 36KB, per-warp 16x64 (+pad)

    int tid  = threadIdx.x;
    int warp = tid >> 5;
    int lane = tid & 31;
    int row0 = blockIdx.x * 128;

    for (int i = tid; i < 4096; i += 256)
        Wh[i] = __float2half(W[i]);
    __syncthreads();

    const __half* ABase = reinterpret_cast<const __half*>(g_agg16);
    int rbase = row0 + warp * 16;           // padding rows in g_agg16 stay zero

    wmma::fragment<wmma::accumulator, 16, 16, 16, float> c[4];
#pragma unroll
    for (int j = 0; j < 4; j++) wmma::fill_fragment(c[j], 0.0f);

#pragma unroll
    for (int kt = 0; kt < 4; kt++) {
        wmma::fragment<wmma::matrix_a, 16, 16, 16, __half, wmma::row_major> a;
        wmma::load_matrix_sync(a, ABase + rbase * 64 + kt * 16, 64);
#pragma unroll
        for (int j = 0; j < 4; j++) {
            wmma::fragment<wmma::matrix_b, 16, 16, 16, __half, wmma::row_major> bf;
            wmma::load_matrix_sync(bf, &Wh[(kt * 16) * 64 + j * 16], 64);
            wmma::mma_sync(c[j], a, bf, c[j]);
        }
    }
#pragma unroll
    for (int j = 0; j < 4; j++)
        wmma::store_matrix_sync(&Cbuf[warp][0][j * 16], c[j], 72, wmma::mem_row_major);
    __syncwarp();

    // epilogue: each lane handles one row-half (16 rows x 2 halves = 32 lanes)
    int r    = lane & 15;
    int half = lane >> 4;          // cols [half*32, half*32+32)
    int grow = rbase + r;
    if (grow < n) {
        float dis = (io_mode != 2) ? g_dis[grow] : 1.0f;
        int cbase = half * 32;
#pragma unroll
        for (int j = 0; j < 8; j++) {
            int cc = cbase + j * 4;
            float4 v = *(const float4*)&Cbuf[warp][r][cc];
            float4 bv = *(const float4*)&b[cc];
            v.x += bv.x; v.y += bv.y; v.z += bv.z; v.w += bv.w;
            if (relu) {
                v.x = fmaxf(v.x, 0.f); v.y = fmaxf(v.y, 0.f);
                v.z = fmaxf(v.z, 0.f); v.w = fmaxf(v.w, 0.f);
            }
            if (outh) {
                v.x *= dis; v.y *= dis; v.z *= dis; v.w *= dis;
                outh[grow * 32 + (cc >> 1)]     = __floats2half2_rn(v.x, v.y);
                outh[grow * 32 + (cc >> 1) + 1] = __floats2half2_rn(v.z, v.w);
            } else {
                *(float4*)&outf[grow * 64 + cc] = v;
            }
        }
    }
}

// ---------------------------------------------------------------------------
extern "C" void kernel_launch(void* const* d_in, const int* in_sizes, int n_in,
                              void* d_out, int out_size) {
    const float* x  = (const float*)d_in[0];
    const void*  ei = d_in[1];
    const float* w  = (const float*)d_in[2];
    const float* W1 = (const float*)d_in[3];
    const float* b1 = (const float*)d_in[4];
    const float* W2 = (const float*)d_in[5];
    const float* b2 = (const float*)d_in[6];
    const float* W3 = (const float*)d_in[7];
    const float* b3 = (const float*)d_in[8];
    float* out = (float*)d_out;

    int n = in_sizes[0] / D;      // 100000
    int E = in_sizes[1] / 2;      // 1600000

    const int tb = 256;
    int nq = n * 16;                         // float4 elements of feature matrix
    int nblk_n = (n + tb - 1) / tb;
    int nblk_c = (nq + tb - 1) / tb;
    int nblk_e = (E + tb - 1) / tb;
    int nb = (n + 1023) / 1024;

    k_prep<<<nblk_n, tb>>>((const long long*)ei, n);
    k_edge_deg<<<nblk_e, tb>>>(ei, w, E, n);
    k_offsets<<<nb, 1024>>>(n);
    k_convert<<<nblk_c, tb>>>(x, nq);
    k_build<<<nblk_e, tb>>>(ei, w, E, n);

    int gblocks = (n * 16 + tb - 1) / tb;   // 2 nodes per warp
    int mblocks = (n + 127) / 128;

    // layer1: hA -> agg -> hB ; layer2: hB -> agg -> hA ; layer3: hA -> out
    k_gather<<<gblocks, tb>>>(0, n);
    k_gemm<<<mblocks, 256>>>(W1, b1, nullptr, 0, n);
    k_gather<<<gblocks, tb>>>(1, n);
    k_gemm<<<mblocks, 256>>>(W2, b2, nullptr, 1, n);
    k_gather<<<gblocks, tb>>>(0, n);
    k_gemm<<<mblocks, 256>>>(W3, b3, out, 2, n);
}